// round 10
// baseline (speedup 1.0000x reference)
#include <cuda_runtime.h>

#define Hh 2048
#define Ww 2048
#define HW (Hh * Ww)
#define TX 32
#define TY 16
#define GBX (Ww / TX)      // 64
#define GBY (Hh / TY)      // 128
#define P1X 36             // padded row stride (logical width 34) for 16B alignment
#define P1Y 18
#define P1N (P1X * P1Y)    // 648 storage; 612 logical
#define SRCX 40            // padded, 16B-aligned staging for src (2-halo + vec align)
#define SRCY 20

// ---------------------------------------------------------------------------
// Fully fused step:
//  - global renormalization skipped (softmax rows sum to 1, MOVES are pure
//    circular shifts => sum(new_mass)==sum(mass) to ~1e-7)
//  - 4 conv kernels combined to 2 (k0+k1, 0.5*(k2+k3))
//  - phase C gather vectorized: 4 output cols per thread, LDS.128/LDS.64
// R7 lesson: NO min-blocks cap (regs<=40 spills). R9 lesson: keep props
// NORMALIZED in smem (inv folded into 9 planes, not 3) — the "optimization"
// of folding inv into state planes regressed 3.6us.
// ---------------------------------------------------------------------------
__global__ void __launch_bounds__(256) step_kernel(
    const float* __restrict__ mass, const float* __restrict__ mom,
    const float* __restrict__ force, const float* __restrict__ A,
    const float* __restrict__ kern, float* __restrict__ out)
{
    __shared__ float s_src[SRCY * SRCX];
    __shared__ float sp[9][P1N];   // normalized propagation weights
    __shared__ float s_m[P1N];     // mass
    __shared__ float smx[P1N];     // updated momentum x
    __shared__ float smy[P1N];     // updated momentum y
    __shared__ float s_w[19];      // w0[9], w1[9], kc

    const int tid = threadIdx.x;
    const int bx = blockIdx.x, by = blockIdx.y;
    const int tx0 = bx * TX;
    const int ty0 = by * TY;
    const bool interior = (bx >= 1) & (bx <= GBX - 2) & (by >= 1) & (by <= GBY - 2);

    if (tid == 0) {
        float ssum = 0.0f;
        #pragma unroll
        for (int j = 0; j < 36; ++j) ssum += fabsf(kern[j]);
        s_w[18] = 1.0f / ssum;
        #pragma unroll
        for (int j = 0; j < 9; ++j) {
            s_w[j]     = kern[j] + kern[9 + j];
            s_w[9 + j] = 0.5f * (kern[18 + j] + kern[27 + j]);
        }
    }

    // ---- Phase A: stage src = A*mass + |force| over 40x20 (2-halo, padded) ----
    if (interior) {
        const float4* m4 = (const float4*)mass;
        const float4* a4 = (const float4*)A;
        const float4* f4 = (const float4*)force;
        const int c0 = (tx0 - 4) >> 2;
        for (int i = tid; i < SRCY * SRCX / 4; i += 256) {   // 200 float4
            int r = i / (SRCX / 4), c = i - r * (SRCX / 4);
            int g4 = (ty0 - 2 + r) * (Ww / 4) + c0 + c;
            float4 m = m4[g4], a = a4[g4];
            float4 fx = f4[g4], fy = f4[HW / 4 + g4];
            float4 s;
            s.x = fmaf(a.x, m.x, sqrtf(fmaf(fx.x, fx.x, fy.x * fy.x)));
            s.y = fmaf(a.y, m.y, sqrtf(fmaf(fx.y, fx.y, fy.y * fy.y)));
            s.z = fmaf(a.z, m.z, sqrtf(fmaf(fx.z, fx.z, fy.z * fy.z)));
            s.w = fmaf(a.w, m.w, sqrtf(fmaf(fx.w, fx.w, fy.w * fy.w)));
            ((float4*)s_src)[i] = s;
        }
    } else {
        for (int i = tid; i < SRCY * SRCX; i += 256) {
            int r = i / SRCX, c = i - r * SRCX;
            int gx = tx0 - 4 + c; if (gx < 0) gx += Ww; else if (gx >= Ww) gx -= Ww;
            int gy = ty0 - 2 + r; if (gy < 0) gy += Hh; else if (gy >= Hh) gy -= Hh;
            int g = gy * Ww + gx;
            float m = mass[g], a = A[g];
            float fx = force[g], fy = force[HW + g];
            s_src[i] = fmaf(a, m, sqrtf(fmaf(fx, fx, fy * fy)));
        }
    }
    __syncthreads();

    float w0[9], w1[9];
    #pragma unroll
    for (int j = 0; j < 9; ++j) { w0[j] = s_w[j]; w1[j] = s_w[9 + j]; }
    const float kc   = s_w[18];
    const float SQ2T = 0.70710678118654752f * 0.1f;

    // ---- Phase B: physics + softmax for the 1-halo region (34x18 logical) ----
    for (int s = tid; s < 34 * P1Y; s += 256) {
        int sy = s / 34, sx = s - sy * 34;
        int st = sy * P1X + sx;              // padded storage index
        int p2 = (sy + 1) * SRCX + sx + 3;

        float nf0 = 0.0f, nf1 = 0.0f;
        #pragma unroll
        for (int r = 0; r < 3; ++r)
            #pragma unroll
            for (int c = 0; c < 3; ++c) {
                float v = s_src[p2 + (r - 1) * SRCX + (c - 1)];
                nf0 = fmaf(v, w0[r * 3 + c], nf0);
                nf1 = fmaf(v, w1[r * 3 + c], nf1);
            }

        int g;
        if (interior) {
            g = (ty0 + sy - 1) * Ww + tx0 + sx - 1;
        } else {
            int gx = tx0 + sx - 1; if (gx < 0) gx += Ww; else if (gx >= Ww) gx -= Ww;
            int gy = ty0 + sy - 1; if (gy < 0) gy += Hh; else if (gy >= Hh) gy -= Hh;
            g = gy * Ww + gx;
        }

        float fx = force[g], fy = force[HW + g];
        float fnx = fx + (nf0 - fx) * kc;
        float fny = fy + (nf1 - fy) * kc;
        float ms = mass[g];

        bool alive = !(ms < 1e-8f);
        float mnx = alive ? (mom[g] + fnx)      : 0.0f;
        float mny = alive ? (mom[HW + g] + fny) : 0.0f;
        float inv_ms = 1.0f / ms;
        float vx = alive ? (mnx * inv_ms) : 0.0f;
        float vy = alive ? (mny * inv_ms) : 0.0f;

        // logits: { l0, l1, l2, l3, 0, -l3, -l2, -l1, -l0 } (temp folded in)
        float sv = SQ2T * vx, sw = SQ2T * vy;
        float l0 = sv + sw;
        float l1 = 0.1f * vy;
        float l2 = sw - sv;
        float l3 = 0.1f * vx;

        float mx = fmaxf(fmaxf(fabsf(l0), fabsf(l1)), fmaxf(fabsf(l2), fabsf(l3)));
        float e0 = __expf(l0 - mx);
        float e1 = __expf(l1 - mx);
        float e2 = __expf(l2 - mx);
        float e3 = __expf(l3 - mx);
        float e4 = __expf(-mx);
        float e5 = __expf(-l3 - mx);
        float e6 = __expf(-l2 - mx);
        float e7 = __expf(-l1 - mx);
        float e8 = __expf(-l0 - mx);
        float inv = 1.0f / (((e0 + e1) + (e2 + e3)) + ((e4 + e5) + (e6 + e7)) + e8);

        sp[0][st] = e0 * inv;  sp[1][st] = e1 * inv;  sp[2][st] = e2 * inv;
        sp[3][st] = e3 * inv;  sp[4][st] = e4 * inv;  sp[5][st] = e5 * inv;
        sp[6][st] = e6 * inv;  sp[7][st] = e7 * inv;  sp[8][st] = e8 * inv;
        s_m[st] = ms;
        smx[st] = mnx;
        smy[st] = mny;

        if (sx >= 1 && sx <= TX && sy >= 1 && sy <= TY) {
            out[3 * HW + g] = fnx;
            out[4 * HW + g] = fny;
        }
    }
    __syncthreads();

    // ---- Phase C: vectorized 3x3 gather, 4 output cols per thread ----
    // term for neighbor offset (dy,dx) uses plane (1-dy)*3 + (1-dx).
    // For staged row rr (dy = rr-1), plane base pb = (2-rr)*3:
    //   dx=-1 -> plane pb+2 at cols ox0..ox0+3
    //   dx= 0 -> plane pb+1 at cols ox0+1..ox0+4
    //   dx=+1 -> plane pb+0 at cols ox0+2..ox0+5
    if (tid < 128) {
        const int k   = tid & 7;      // col group
        const int row = tid >> 3;     // output row 0..15
        const int ox0 = k * 4;

        float am0 = 0.f, am1 = 0.f, am2 = 0.f, am3 = 0.f;
        float ax0 = 0.f, ax1 = 0.f, ax2 = 0.f, ax3 = 0.f;
        float ay0 = 0.f, ay1 = 0.f, ay2 = 0.f, ay3 = 0.f;

        #pragma unroll
        for (int rr = 0; rr < 3; ++rr) {
            const int base = (row + rr) * P1X + ox0;
            const int pb = (2 - rr) * 3;

            // prop windows (shared across the 3 quantities)
            float4 pA  = *(const float4*)&sp[pb + 2][base];      // dx=-1 : cols 0..3
            float4 pB0 = *(const float4*)&sp[pb + 1][base];      // dx= 0 : cols 1..4
            float  pB4 = sp[pb + 1][base + 4];
            float2 pC0 = *(const float2*)&sp[pb + 0][base + 2];  // dx=+1 : cols 2..5
            float2 pC1 = *(const float2*)&sp[pb + 0][base + 4];

            // mass row
            {
                float4 q4 = *(const float4*)&s_m[base];
                float2 q2 = *(const float2*)&s_m[base + 4];
                am0 = fmaf(q4.x, pA.x, am0); am1 = fmaf(q4.y, pA.y, am1);
                am2 = fmaf(q4.z, pA.z, am2); am3 = fmaf(q4.w, pA.w, am3);
                am0 = fmaf(q4.y, pB0.y, am0); am1 = fmaf(q4.z, pB0.z, am1);
                am2 = fmaf(q4.w, pB0.w, am2); am3 = fmaf(q2.x, pB4,  am3);
                am0 = fmaf(q4.z, pC0.x, am0); am1 = fmaf(q4.w, pC0.y, am1);
                am2 = fmaf(q2.x, pC1.x, am2); am3 = fmaf(q2.y, pC1.y, am3);
            }
            // momentum x row
            {
                float4 q4 = *(const float4*)&smx[base];
                float2 q2 = *(const float2*)&smx[base + 4];
                ax0 = fmaf(q4.x, pA.x, ax0); ax1 = fmaf(q4.y, pA.y, ax1);
                ax2 = fmaf(q4.z, pA.z, ax2); ax3 = fmaf(q4.w, pA.w, ax3);
                ax0 = fmaf(q4.y, pB0.y, ax0); ax1 = fmaf(q4.z, pB0.z, ax1);
                ax2 = fmaf(q4.w, pB0.w, ax2); ax3 = fmaf(q2.x, pB4,  ax3);
                ax0 = fmaf(q4.z, pC0.x, ax0); ax1 = fmaf(q4.w, pC0.y, ax1);
                ax2 = fmaf(q2.x, pC1.x, ax2); ax3 = fmaf(q2.y, pC1.y, ax3);
            }
            // momentum y row
            {
                float4 q4 = *(const float4*)&smy[base];
                float2 q2 = *(const float2*)&smy[base + 4];
                ay0 = fmaf(q4.x, pA.x, ay0); ay1 = fmaf(q4.y, pA.y, ay1);
                ay2 = fmaf(q4.z, pA.z, ay2); ay3 = fmaf(q4.w, pA.w, ay3);
                ay0 = fmaf(q4.y, pB0.y, ay0); ay1 = fmaf(q4.z, pB0.z, ay1);
                ay2 = fmaf(q4.w, pB0.w, ay2); ay3 = fmaf(q2.x, pB4,  ay3);
                ay0 = fmaf(q4.z, pC0.x, ay0); ay1 = fmaf(q4.w, pC0.y, ay1);
                ay2 = fmaf(q2.x, pC1.x, ay2); ay3 = fmaf(q2.y, pC1.y, ay3);
            }
        }

        const int g = (ty0 + row) * Ww + tx0 + ox0;
        *(float4*)&out[g]          = make_float4(am0, am1, am2, am3);
        *(float4*)&out[HW + g]     = make_float4(ax0, ax1, ax2, ax3);
        *(float4*)&out[2 * HW + g] = make_float4(ay0, ay1, ay2, ay3);
    }
}

// ---------------------------------------------------------------------------
extern "C" void kernel_launch(void* const* d_in, const int* in_sizes, int n_in,
                              void* d_out, int out_size) {
    const float* mass = (const float*)d_in[0];   // (1,1,H,W)
    const float* mom  = (const float*)d_in[1];   // (2,1,H,W)
    const float* forc = (const float*)d_in[2];   // (2,1,H,W)
    const float* A    = (const float*)d_in[3];   // (1,1,H,W)
    const float* kern = (const float*)d_in[4];   // (4,1,3,3)
    float* out = (float*)d_out;                  // [new_mass | new_mom(2) | force(2)]

    dim3 grid(GBX, GBY);
    step_kernel<<<grid, 256>>>(mass, mom, forc, A, kern, out);
}

// round 11
// speedup vs baseline: 1.0953x; 1.0953x over previous
#include <cuda_runtime.h>

#define Hh 2048
#define Ww 2048
#define HW (Hh * Ww)
#define TX 32
#define TY 16
#define GBX (Ww / TX)      // 64
#define GBY (Hh / TY)      // 128
#define P1X 34
#define P1Y 18
#define P1N (P1X * P1Y)    // 612 : 1-halo region (props / state)
#define SRCX 40            // padded, 16B-aligned staging for src (2-halo + vec align)
#define SRCY 20

// ---------------------------------------------------------------------------
// Fully fused step (R6 structure — proven 76.3us):
//  - global renormalization skipped (softmax rows sum to 1, MOVES are pure
//    circular shifts => sum(new_mass)==sum(mass) to ~1e-7)
//  - 4 conv kernels combined to 2 (k0+k1, 0.5*(k2+k3))
// Lessons encoded: no reg caps (R7 spill), no inv-folding (R9), no vector
// phase C (R10: regs 62 -> occ 44%). This round: (mx,my) float2 packing +
// branch-free B unroll — instruction cuts at identical wavefronts/regs.
// ---------------------------------------------------------------------------
__global__ void __launch_bounds__(256) step_kernel(
    const float* __restrict__ mass, const float* __restrict__ mom,
    const float* __restrict__ force, const float* __restrict__ A,
    const float* __restrict__ kern, float* __restrict__ out)
{
    __shared__ float  s_src[SRCY * SRCX];
    __shared__ float  sp[9][P1N];   // normalized propagation weights
    __shared__ float  s_m[P1N];     // mass
    __shared__ float2 smxy[P1N];    // updated momentum (x,y) packed
    __shared__ float  s_w[19];      // w0[9], w1[9], kc

    const int tid = threadIdx.x;
    const int bx = blockIdx.x, by = blockIdx.y;
    const int tx0 = bx * TX;
    const int ty0 = by * TY;
    const bool interior = (bx >= 1) & (bx <= GBX - 2) & (by >= 1) & (by <= GBY - 2);

    if (tid == 0) {
        float ssum = 0.0f;
        #pragma unroll
        for (int j = 0; j < 36; ++j) ssum += fabsf(kern[j]);
        s_w[18] = 1.0f / ssum;
        #pragma unroll
        for (int j = 0; j < 9; ++j) {
            s_w[j]     = kern[j] + kern[9 + j];
            s_w[9 + j] = 0.5f * (kern[18 + j] + kern[27 + j]);
        }
    }

    // ---- Phase A: stage src = A*mass + |force| over 40x20 (2-halo, padded) ----
    if (interior) {
        const float4* m4 = (const float4*)mass;
        const float4* a4 = (const float4*)A;
        const float4* f4 = (const float4*)force;
        const int c0 = (tx0 - 4) >> 2;
        for (int i = tid; i < SRCY * SRCX / 4; i += 256) {   // 200 float4
            int r = i / (SRCX / 4), c = i - r * (SRCX / 4);
            int g4 = (ty0 - 2 + r) * (Ww / 4) + c0 + c;
            float4 m = m4[g4], a = a4[g4];
            float4 fx = f4[g4], fy = f4[HW / 4 + g4];
            float4 s;
            s.x = fmaf(a.x, m.x, sqrtf(fmaf(fx.x, fx.x, fy.x * fy.x)));
            s.y = fmaf(a.y, m.y, sqrtf(fmaf(fx.y, fx.y, fy.y * fy.y)));
            s.z = fmaf(a.z, m.z, sqrtf(fmaf(fx.z, fx.z, fy.z * fy.z)));
            s.w = fmaf(a.w, m.w, sqrtf(fmaf(fx.w, fx.w, fy.w * fy.w)));
            ((float4*)s_src)[i] = s;
        }
    } else {
        for (int i = tid; i < SRCY * SRCX; i += 256) {
            int r = i / SRCX, c = i - r * SRCX;
            int gx = tx0 - 4 + c; if (gx < 0) gx += Ww; else if (gx >= Ww) gx -= Ww;
            int gy = ty0 - 2 + r; if (gy < 0) gy += Hh; else if (gy >= Hh) gy -= Hh;
            int g = gy * Ww + gx;
            float m = mass[g], a = A[g];
            float fx = force[g], fy = force[HW + g];
            s_src[i] = fmaf(a, m, sqrtf(fmaf(fx, fx, fy * fy)));
        }
    }
    __syncthreads();

    float w0[9], w1[9];
    #pragma unroll
    for (int j = 0; j < 9; ++j) { w0[j] = s_w[j]; w1[j] = s_w[9 + j]; }
    const float kc   = s_w[18];
    const float SQ2T = 0.70710678118654752f * 0.1f;

    // ---- Phase B: physics + softmax for the 1-halo region (34x18) ----
    auto bbody = [&](int s) {
        int sy = s / P1X, sx = s - sy * P1X;
        int p2 = (sy + 1) * SRCX + sx + 3;

        float nf0 = 0.0f, nf1 = 0.0f;
        #pragma unroll
        for (int r = 0; r < 3; ++r)
            #pragma unroll
            for (int c = 0; c < 3; ++c) {
                float v = s_src[p2 + (r - 1) * SRCX + (c - 1)];
                nf0 = fmaf(v, w0[r * 3 + c], nf0);
                nf1 = fmaf(v, w1[r * 3 + c], nf1);
            }

        int g;
        if (interior) {
            g = (ty0 + sy - 1) * Ww + tx0 + sx - 1;
        } else {
            int gx = tx0 + sx - 1; if (gx < 0) gx += Ww; else if (gx >= Ww) gx -= Ww;
            int gy = ty0 + sy - 1; if (gy < 0) gy += Hh; else if (gy >= Hh) gy -= Hh;
            g = gy * Ww + gx;
        }

        float fx = force[g], fy = force[HW + g];
        float fnx = fx + (nf0 - fx) * kc;
        float fny = fy + (nf1 - fy) * kc;
        float ms = mass[g];

        bool alive = !(ms < 1e-8f);
        float mnx = alive ? (mom[g] + fnx)      : 0.0f;
        float mny = alive ? (mom[HW + g] + fny) : 0.0f;
        float inv_ms = 1.0f / ms;
        float vx = alive ? (mnx * inv_ms) : 0.0f;
        float vy = alive ? (mny * inv_ms) : 0.0f;

        // logits: { l0, l1, l2, l3, 0, -l3, -l2, -l1, -l0 } (temp folded in)
        float sv = SQ2T * vx, sw = SQ2T * vy;
        float l0 = sv + sw;
        float l1 = 0.1f * vy;
        float l2 = sw - sv;
        float l3 = 0.1f * vx;

        float mx = fmaxf(fmaxf(fabsf(l0), fabsf(l1)), fmaxf(fabsf(l2), fabsf(l3)));
        float e0 = __expf(l0 - mx);
        float e1 = __expf(l1 - mx);
        float e2 = __expf(l2 - mx);
        float e3 = __expf(l3 - mx);
        float e4 = __expf(-mx);
        float e5 = __expf(-l3 - mx);
        float e6 = __expf(-l2 - mx);
        float e7 = __expf(-l1 - mx);
        float e8 = __expf(-l0 - mx);
        float inv = 1.0f / (((e0 + e1) + (e2 + e3)) + ((e4 + e5) + (e6 + e7)) + e8);

        sp[0][s] = e0 * inv;  sp[1][s] = e1 * inv;  sp[2][s] = e2 * inv;
        sp[3][s] = e3 * inv;  sp[4][s] = e4 * inv;  sp[5][s] = e5 * inv;
        sp[6][s] = e6 * inv;  sp[7][s] = e7 * inv;  sp[8][s] = e8 * inv;
        s_m[s]  = ms;
        smxy[s] = make_float2(mnx, mny);

        if (sx >= 1 && sx <= TX && sy >= 1 && sy <= TY) {
            out[3 * HW + g] = fnx;
            out[4 * HW + g] = fny;
        }
    };
    // 612 = 2*256 + 100 : two unconditional iterations + predicated tail
    bbody(tid);
    bbody(tid + 256);
    if (tid < P1N - 512) bbody(tid + 512);
    __syncthreads();

    // ---- Phase C: 3x3 gather, 2-row strip per thread, float2 state reads ----
    {
        const int ltx = tid & 31;
        const int lty = tid >> 5;
        const int oyA = lty * 2;
        float amA = 0.f, axA = 0.f, ayA = 0.f;
        float amB = 0.f, axB = 0.f, ayB = 0.f;

        #pragma unroll
        for (int r = 0; r < 4; ++r) {
            int rb = (oyA + r) * P1X + ltx;
            float  qm0 = s_m[rb], qm1 = s_m[rb + 1], qm2 = s_m[rb + 2];
            float2 q0 = smxy[rb], q1 = smxy[rb + 1], q2 = smxy[rb + 2];

            if (r <= 2) {   // pixel A, dy = r-1, plane base (2-r)*3
                float p;
                p = sp[(2 - r) * 3 + 0][rb + 2];
                amA = fmaf(qm2, p, amA); axA = fmaf(q2.x, p, axA); ayA = fmaf(q2.y, p, ayA);
                p = sp[(2 - r) * 3 + 1][rb + 1];
                amA = fmaf(qm1, p, amA); axA = fmaf(q1.x, p, axA); ayA = fmaf(q1.y, p, ayA);
                p = sp[(2 - r) * 3 + 2][rb];
                amA = fmaf(qm0, p, amA); axA = fmaf(q0.x, p, axA); ayA = fmaf(q0.y, p, ayA);
            }
            if (r >= 1) {   // pixel B, dy = r-2, plane base (3-r)*3
                float p;
                p = sp[(3 - r) * 3 + 0][rb + 2];
                amB = fmaf(qm2, p, amB); axB = fmaf(q2.x, p, axB); ayB = fmaf(q2.y, p, ayB);
                p = sp[(3 - r) * 3 + 1][rb + 1];
                amB = fmaf(qm1, p, amB); axB = fmaf(q1.x, p, axB); ayB = fmaf(q1.y, p, ayB);
                p = sp[(3 - r) * 3 + 2][rb];
                amB = fmaf(qm0, p, amB); axB = fmaf(q0.x, p, axB); ayB = fmaf(q0.y, p, ayB);
            }
        }

        int gA = (ty0 + oyA) * Ww + tx0 + ltx;
        out[gA]               = amA;
        out[HW + gA]          = axA;
        out[2 * HW + gA]      = ayA;
        out[gA + Ww]          = amB;
        out[HW + gA + Ww]     = axB;
        out[2 * HW + gA + Ww] = ayB;
    }
}

// ---------------------------------------------------------------------------
extern "C" void kernel_launch(void* const* d_in, const int* in_sizes, int n_in,
                              void* d_out, int out_size) {
    const float* mass = (const float*)d_in[0];   // (1,1,H,W)
    const float* mom  = (const float*)d_in[1];   // (2,1,H,W)
    const float* forc = (const float*)d_in[2];   // (2,1,H,W)
    const float* A    = (const float*)d_in[3];   // (1,1,H,W)
    const float* kern = (const float*)d_in[4];   // (4,1,3,3)
    float* out = (float*)d_out;                  // [new_mass | new_mom(2) | force(2)]

    dim3 grid(GBX, GBY);
    step_kernel<<<grid, 256>>>(mass, mom, forc, A, kern, out);
}

// round 12
// speedup vs baseline: 1.0995x; 1.0038x over previous
#include <cuda_runtime.h>

#define Hh 2048
#define Ww 2048
#define HW (Hh * Ww)
#define TX 32
#define TY 16
#define GBX (Ww / TX)      // 64
#define GBY (Hh / TY)      // 128
#define P1X 34
#define P1Y 18
#define P1N (P1X * P1Y)    // 612 : 1-halo region (props / state)
#define SRCX 40            // padded, 16B-aligned staging for src (2-halo + vec align)
#define SRCY 20

// ---------------------------------------------------------------------------
// Fully fused step (R6 structure, proven):
//  - global renormalization skipped (softmax rows sum to 1, MOVES are pure
//    circular shifts => sum(new_mass)==sum(mass) to ~1e-7)
//  - 4 conv kernels combined to 2 (k0+k1, 0.5*(k2+k3))
//  - (mx,my) packed float2 in smem (R11: real instruction cut)
// Lessons: regs must stay <=~50 (occ tracks regs: 5blk@48, 4blk@59,
// spill@40-cap). So: NO manual B unroll (R11), no reg caps (R7), no
// inv-folding (R9), no vector phase C (R10).
// ---------------------------------------------------------------------------
__global__ void __launch_bounds__(256) step_kernel(
    const float* __restrict__ mass, const float* __restrict__ mom,
    const float* __restrict__ force, const float* __restrict__ A,
    const float* __restrict__ kern, float* __restrict__ out)
{
    __shared__ float  s_src[SRCY * SRCX];
    __shared__ float  sp[9][P1N];   // normalized propagation weights
    __shared__ float  s_m[P1N];     // mass
    __shared__ float2 smxy[P1N];    // updated momentum (x,y) packed
    __shared__ float  s_w[19];      // w0[9], w1[9], kc

    const int tid = threadIdx.x;
    const int bx = blockIdx.x, by = blockIdx.y;
    const int tx0 = bx * TX;
    const int ty0 = by * TY;
    const bool interior = (bx >= 1) & (bx <= GBX - 2) & (by >= 1) & (by <= GBY - 2);

    if (tid == 0) {
        float ssum = 0.0f;
        #pragma unroll
        for (int j = 0; j < 36; ++j) ssum += fabsf(kern[j]);
        s_w[18] = 1.0f / ssum;
        #pragma unroll
        for (int j = 0; j < 9; ++j) {
            s_w[j]     = kern[j] + kern[9 + j];
            s_w[9 + j] = 0.5f * (kern[18 + j] + kern[27 + j]);
        }
    }

    // ---- Phase A: stage src = A*mass + |force| over 40x20 (2-halo, padded) ----
    if (interior) {
        const float4* m4 = (const float4*)mass;
        const float4* a4 = (const float4*)A;
        const float4* f4 = (const float4*)force;
        const int c0 = (tx0 - 4) >> 2;
        for (int i = tid; i < SRCY * SRCX / 4; i += 256) {   // 200 float4
            int r = i / (SRCX / 4), c = i - r * (SRCX / 4);
            int g4 = (ty0 - 2 + r) * (Ww / 4) + c0 + c;
            float4 m = m4[g4], a = a4[g4];
            float4 fx = f4[g4], fy = f4[HW / 4 + g4];
            float4 s;
            s.x = fmaf(a.x, m.x, sqrtf(fmaf(fx.x, fx.x, fy.x * fy.x)));
            s.y = fmaf(a.y, m.y, sqrtf(fmaf(fx.y, fx.y, fy.y * fy.y)));
            s.z = fmaf(a.z, m.z, sqrtf(fmaf(fx.z, fx.z, fy.z * fy.z)));
            s.w = fmaf(a.w, m.w, sqrtf(fmaf(fx.w, fx.w, fy.w * fy.w)));
            ((float4*)s_src)[i] = s;
        }
    } else {
        for (int i = tid; i < SRCY * SRCX; i += 256) {
            int r = i / SRCX, c = i - r * SRCX;
            int gx = tx0 - 4 + c; if (gx < 0) gx += Ww; else if (gx >= Ww) gx -= Ww;
            int gy = ty0 - 2 + r; if (gy < 0) gy += Hh; else if (gy >= Hh) gy -= Hh;
            int g = gy * Ww + gx;
            float m = mass[g], a = A[g];
            float fx = force[g], fy = force[HW + g];
            s_src[i] = fmaf(a, m, sqrtf(fmaf(fx, fx, fy * fy)));
        }
    }
    __syncthreads();

    float w0[9], w1[9];
    #pragma unroll
    for (int j = 0; j < 9; ++j) { w0[j] = s_w[j]; w1[j] = s_w[9 + j]; }
    const float kc   = s_w[18];
    const float SQ2T = 0.70710678118654752f * 0.1f;

    // ---- Phase B: physics + softmax for the 1-halo region (34x18) ----
    for (int s = tid; s < P1N; s += 256) {
        int sy = s / P1X, sx = s - sy * P1X;
        int p2 = (sy + 1) * SRCX + sx + 3;

        float nf0 = 0.0f, nf1 = 0.0f;
        #pragma unroll
        for (int r = 0; r < 3; ++r)
            #pragma unroll
            for (int c = 0; c < 3; ++c) {
                float v = s_src[p2 + (r - 1) * SRCX + (c - 1)];
                nf0 = fmaf(v, w0[r * 3 + c], nf0);
                nf1 = fmaf(v, w1[r * 3 + c], nf1);
            }

        int g;
        if (interior) {
            g = (ty0 + sy - 1) * Ww + tx0 + sx - 1;
        } else {
            int gx = tx0 + sx - 1; if (gx < 0) gx += Ww; else if (gx >= Ww) gx -= Ww;
            int gy = ty0 + sy - 1; if (gy < 0) gy += Hh; else if (gy >= Hh) gy -= Hh;
            g = gy * Ww + gx;
        }

        float fx = force[g], fy = force[HW + g];
        float fnx = fx + (nf0 - fx) * kc;
        float fny = fy + (nf1 - fy) * kc;
        float ms = mass[g];

        bool alive = !(ms < 1e-8f);
        float mnx = alive ? (mom[g] + fnx)      : 0.0f;
        float mny = alive ? (mom[HW + g] + fny) : 0.0f;
        float inv_ms = 1.0f / ms;
        float vx = alive ? (mnx * inv_ms) : 0.0f;
        float vy = alive ? (mny * inv_ms) : 0.0f;

        // logits: { l0, l1, l2, l3, 0, -l3, -l2, -l1, -l0 } (temp folded in)
        float sv = SQ2T * vx, sw = SQ2T * vy;
        float l0 = sv + sw;
        float l1 = 0.1f * vy;
        float l2 = sw - sv;
        float l3 = 0.1f * vx;

        float mx = fmaxf(fmaxf(fabsf(l0), fabsf(l1)), fmaxf(fabsf(l2), fabsf(l3)));
        float e0 = __expf(l0 - mx);
        float e1 = __expf(l1 - mx);
        float e2 = __expf(l2 - mx);
        float e3 = __expf(l3 - mx);
        float e4 = __expf(-mx);
        float e5 = __expf(-l3 - mx);
        float e6 = __expf(-l2 - mx);
        float e7 = __expf(-l1 - mx);
        float e8 = __expf(-l0 - mx);
        float inv = 1.0f / (((e0 + e1) + (e2 + e3)) + ((e4 + e5) + (e6 + e7)) + e8);

        sp[0][s] = e0 * inv;  sp[1][s] = e1 * inv;  sp[2][s] = e2 * inv;
        sp[3][s] = e3 * inv;  sp[4][s] = e4 * inv;  sp[5][s] = e5 * inv;
        sp[6][s] = e6 * inv;  sp[7][s] = e7 * inv;  sp[8][s] = e8 * inv;
        s_m[s]  = ms;
        smxy[s] = make_float2(mnx, mny);

        if (sx >= 1 && sx <= TX && sy >= 1 && sy <= TY) {
            out[3 * HW + g] = fnx;
            out[4 * HW + g] = fny;
        }
    }
    __syncthreads();

    // ---- Phase C: 3x3 gather, 2-row strip per thread, float2 state reads ----
    {
        const int ltx = tid & 31;
        const int lty = tid >> 5;
        const int oyA = lty * 2;
        float amA = 0.f, axA = 0.f, ayA = 0.f;
        float amB = 0.f, axB = 0.f, ayB = 0.f;

        #pragma unroll
        for (int r = 0; r < 4; ++r) {
            int rb = (oyA + r) * P1X + ltx;
            float  qm0 = s_m[rb], qm1 = s_m[rb + 1], qm2 = s_m[rb + 2];
            float2 q0 = smxy[rb], q1 = smxy[rb + 1], q2 = smxy[rb + 2];

            if (r <= 2) {   // pixel A, dy = r-1, plane base (2-r)*3
                float p;
                p = sp[(2 - r) * 3 + 0][rb + 2];
                amA = fmaf(qm2, p, amA); axA = fmaf(q2.x, p, axA); ayA = fmaf(q2.y, p, ayA);
                p = sp[(2 - r) * 3 + 1][rb + 1];
                amA = fmaf(qm1, p, amA); axA = fmaf(q1.x, p, axA); ayA = fmaf(q1.y, p, ayA);
                p = sp[(2 - r) * 3 + 2][rb];
                amA = fmaf(qm0, p, amA); axA = fmaf(q0.x, p, axA); ayA = fmaf(q0.y, p, ayA);
            }
            if (r >= 1) {   // pixel B, dy = r-2, plane base (3-r)*3
                float p;
                p = sp[(3 - r) * 3 + 0][rb + 2];
                amB = fmaf(qm2, p, amB); axB = fmaf(q2.x, p, axB); ayB = fmaf(q2.y, p, ayB);
                p = sp[(3 - r) * 3 + 1][rb + 1];
                amB = fmaf(qm1, p, amB); axB = fmaf(q1.x, p, axB); ayB = fmaf(q1.y, p, ayB);
                p = sp[(3 - r) * 3 + 2][rb];
                amB = fmaf(qm0, p, amB); axB = fmaf(q0.x, p, axB); ayB = fmaf(q0.y, p, ayB);
            }
        }

        int gA = (ty0 + oyA) * Ww + tx0 + ltx;
        out[gA]               = amA;
        out[HW + gA]          = axA;
        out[2 * HW + gA]      = ayA;
        out[gA + Ww]          = amB;
        out[HW + gA + Ww]     = axB;
        out[2 * HW + gA + Ww] = ayB;
    }
}

// ---------------------------------------------------------------------------
extern "C" void kernel_launch(void* const* d_in, const int* in_sizes, int n_in,
                              void* d_out, int out_size) {
    const float* mass = (const float*)d_in[0];   // (1,1,H,W)
    const float* mom  = (const float*)d_in[1];   // (2,1,H,W)
    const float* forc = (const float*)d_in[2];   // (2,1,H,W)
    const float* A    = (const float*)d_in[3];   // (1,1,H,W)
    const float* kern = (const float*)d_in[4];   // (4,1,3,3)
    float* out = (float*)d_out;                  // [new_mass | new_mom(2) | force(2)]

    dim3 grid(GBX, GBY);
    step_kernel<<<grid, 256>>>(mass, mom, forc, A, kern, out);
}